// round 5
// baseline (speedup 1.0000x reference)
#include <cuda_runtime.h>

// LePEAttention: B=4, C=64, H=W=128, NUM_HEADS=8, hd=8, SPLIT=2
// -> H_sp=128, W_sp=2, no padding. 2048 CTAs = (batch, window, head).
// R5: 64 threads/CTA, 4 queries per thread (t, t+64, t+128, t+192).
// LDS per key is shared across 4 queries -> inner-loop LDS ops halved vs R4
// (the shared LDS-return path was the binder: occ 23->28% changed nothing).
// launch_bounds(64,8) = 128-reg budget; persistent state ~68 regs; unroll 2.

#define HW_  (128*128)
#define WW_  128
#define CC_  64
#define LOG2E 1.44269504088896340736f

__device__ __forceinline__ unsigned long long pk2(float lo, float hi) {
    unsigned long long r;
    asm("mov.b64 %0, {%1, %2};" : "=l"(r) : "f"(lo), "f"(hi));
    return r;
}
__device__ __forceinline__ void upk2(unsigned long long v, float& lo, float& hi) {
    asm("mov.b64 {%0, %1}, %2;" : "=f"(lo), "=f"(hi) : "l"(v));
}
__device__ __forceinline__ unsigned long long ffma2(unsigned long long a, unsigned long long b, unsigned long long c) {
    unsigned long long d;
    asm("fma.rn.f32x2 %0, %1, %2, %3;" : "=l"(d) : "l"(a), "l"(b), "l"(c));
    return d;
}
__device__ __forceinline__ unsigned long long fmul2(unsigned long long a, unsigned long long b) {
    unsigned long long d;
    asm("mul.rn.f32x2 %0, %1, %2;" : "=l"(d) : "l"(a), "l"(b));
    return d;
}
__device__ __forceinline__ unsigned long long fadd2(unsigned long long a, unsigned long long b) {
    unsigned long long d;
    asm("add.rn.f32x2 %0, %1, %2;" : "=l"(d) : "l"(a), "l"(b));
    return d;
}
__device__ __forceinline__ float ex2(float x) {
    float r;
    asm("ex2.approx.f32 %0, %1;" : "=f"(r) : "f"(x));
    return r;
}

__global__ void __launch_bounds__(64, 8)
lepe_kernel(const float* __restrict__ temp,
            const float* __restrict__ cw,
            const float* __restrict__ cb,
            float* __restrict__ out)
{
    const int wh  = blockIdx.x;      // 0..2047
    const int h   = wh & 7;          // head
    const int win = wh >> 3;         // 0..255
    const int b   = win >> 6;        // batch
    const int wx  = win & 63;        // window column (x in [2*wx, 2*wx+1])
    const int t   = threadIdx.x;     // 0..63; owns queries t + 64*{0,1,2,3}

    __shared__ __align__(16) float qS[256*8];
    __shared__ __align__(16) float kS[256*8];
    __shared__ __align__(16) float vS[262*8];   // 3 guard-zero tokens each side
    __shared__ __align__(16) float wS[9*8];
    __shared__ float bS[8];

    if (t < 24) { vS[t] = 0.f; vS[262*8 - 24 + t] = 0.f; }
    for (int idx = t; idx < 72; idx += 64)
        wS[idx] = cw[(h*8 + (idx & 7))*9 + (idx >> 3)];     // wS[tap][d]
    if (t < 8)  bS[t] = cb[h*8 + t];

    // Cooperative tile load: thread -> (d = t&7, y0 = t>>3 in 0..7), 16 steps.
    {
        const int d  = t & 7;
        const int y0 = t >> 3;
        const size_t cbase = (size_t)(h*8 + d) * HW_ + 2*wx;
        const float* qg = temp + (size_t)(b*3 + 0)*CC_*HW_ + cbase;
        const float* kg = temp + (size_t)(b*3 + 1)*CC_*HW_ + cbase;
        const float* vg = temp + (size_t)(b*3 + 2)*CC_*HW_ + cbase;
        #pragma unroll
        for (int i = 0; i < 16; i++) {
            int y = y0 + i*8;
            float2 q2 = *(const float2*)(qg + (size_t)y*WW_);
            float2 k2 = *(const float2*)(kg + (size_t)y*WW_);
            float2 v2 = *(const float2*)(vg + (size_t)y*WW_);
            qS[(2*y  )*8 + d] = q2.x;  qS[(2*y+1)*8 + d] = q2.y;
            kS[(2*y  )*8 + d] = k2.x;  kS[(2*y+1)*8 + d] = k2.y;
            vS[(3+2*y)*8 + d] = v2.x;  vS[(4+2*y)*8 + d] = v2.y;
        }
    }
    __syncthreads();

    // Four query rows per thread; fold scale*log2(e) into Q so softmax is a
    // bare ex2.approx per (query, key).
    const float qscale = 0.35355339059327373f * LOG2E;  // 8^-0.5 * log2(e)
    unsigned long long q[4][4];
    #pragma unroll
    for (int qi = 0; qi < 4; qi++) {
        const int tok = t + qi*64;
        float4 x0 = *(const float4*)&qS[tok*8];
        float4 x1 = *(const float4*)&qS[tok*8 + 4];
        q[qi][0] = pk2(x0.x*qscale, x0.y*qscale);
        q[qi][1] = pk2(x0.z*qscale, x0.w*qscale);
        q[qi][2] = pk2(x1.x*qscale, x1.y*qscale);
        q[qi][3] = pk2(x1.z*qscale, x1.w*qscale);
    }

    unsigned long long acc[4][4];
    #pragma unroll
    for (int qi = 0; qi < 4; qi++)
        #pragma unroll
        for (int d = 0; d < 4; d++) acc[qi][d] = 0ull;
    unsigned long long l01 = 0ull, l23 = 0ull;

    const ulonglong2* k128 = (const ulonglong2*)kS;
    const ulonglong2* v128 = (const ulonglong2*)(vS + 24);  // token 0 of V

    #pragma unroll 2
    for (int j = 0; j < 256; j++) {
        ulonglong2 ka = k128[j*2 + 0];   // k[j][0..3]
        ulonglong2 kb = k128[j*2 + 1];   // k[j][4..7]
        ulonglong2 va = v128[j*2 + 0];
        ulonglong2 vb = v128[j*2 + 1];

        float p[4];
        #pragma unroll
        for (int qi = 0; qi < 4; qi++) {
            unsigned long long d0 = fmul2(q[qi][0], ka.x);
            d0 = ffma2(q[qi][1], ka.y, d0);
            d0 = ffma2(q[qi][2], kb.x, d0);
            d0 = ffma2(q[qi][3], kb.y, d0);
            float slo, shi;
            upk2(d0, slo, shi);
            p[qi] = ex2(slo + shi);
        }
        l01 = fadd2(l01, pk2(p[0], p[1]));
        l23 = fadd2(l23, pk2(p[2], p[3]));

        #pragma unroll
        for (int qi = 0; qi < 4; qi++) {
            unsigned long long pp = pk2(p[qi], p[qi]);
            acc[qi][0] = ffma2(pp, va.x, acc[qi][0]);
            acc[qi][1] = ffma2(pp, va.y, acc[qi][1]);
            acc[qi][2] = ffma2(pp, vb.x, acc[qi][2]);
            acc[qi][3] = ffma2(pp, vb.y, acc[qi][3]);
        }
    }

    float lv[4];
    upk2(l01, lv[0], lv[1]);
    upk2(l23, lv[2], lv[3]);

    // Epilogue per owned query token: softmax normalize + LePE depthwise 3x3
    // conv on the V tile in SMEM, then one float4-pair store.
    #pragma unroll
    for (int qi = 0; qi < 4; qi++) {
        const int tok = t + qi*64;
        const float inv = 1.0f / lv[qi];
        float o[8];
        upk2(acc[qi][0], o[0], o[1]);
        upk2(acc[qi][1], o[2], o[3]);
        upk2(acc[qi][2], o[4], o[5]);
        upk2(acc[qi][3], o[6], o[7]);

        const int y  = tok >> 1;
        const int xi = tok & 1;
        float r[8];
        #pragma unroll
        for (int d = 0; d < 8; d++) r[d] = bS[d];
        #pragma unroll
        for (int ky = 0; ky < 3; ky++) {
            #pragma unroll
            for (int kx = 0; kx < 3; kx++) {
                int dxi = xi + kx - 1;
                if (dxi >= 0 && dxi <= 1) {
                    int ptok = tok + (ky - 1)*2 + (kx - 1) + 3;  // padded index
                    const float4 va = *(const float4*)&vS[ptok*8];
                    const float4 vb = *(const float4*)&vS[ptok*8 + 4];
                    const float4 wa = *(const float4*)&wS[(ky*3 + kx)*8];
                    const float4 wb = *(const float4*)&wS[(ky*3 + kx)*8 + 4];
                    r[0] += va.x*wa.x;  r[1] += va.y*wa.y;
                    r[2] += va.z*wa.z;  r[3] += va.w*wa.w;
                    r[4] += vb.x*wb.x;  r[5] += vb.y*wb.y;
                    r[6] += vb.z*wb.z;  r[7] += vb.w*wb.w;
                }
            }
        }

        const size_t obase = ((size_t)b*HW_ + (size_t)y*WW_ + 2*wx + xi)*CC_ + h*8;
        float4 w0 = make_float4(o[0]*inv + r[0], o[1]*inv + r[1],
                                o[2]*inv + r[2], o[3]*inv + r[3]);
        float4 w1 = make_float4(o[4]*inv + r[4], o[5]*inv + r[5],
                                o[6]*inv + r[6], o[7]*inv + r[7]);
        *(float4*)(out + obase)     = w0;
        *(float4*)(out + obase + 4) = w1;
    }
}

extern "C" void kernel_launch(void* const* d_in, const int* in_sizes, int n_in,
                              void* d_out, int out_size)
{
    const float* temp = (const float*)d_in[0];
    const float* cw   = (const float*)d_in[1];
    const float* cb   = (const float*)d_in[2];
    float* out        = (float*)d_out;
    lepe_kernel<<<2048, 64>>>(temp, cw, cb, out);
}

// round 6
// speedup vs baseline: 1.1187x; 1.1187x over previous
#include <cuda_runtime.h>

// LePEAttention: B=4, C=64, H=W=128, NUM_HEADS=8, hd=8, SPLIT=2
// -> H_sp=128, W_sp=2, no padding. 2048 CTAs = (batch, window, head).
// R6: R3 config (128 thr, 2 queries/thread) + key-pair-transposed K layout:
// kT[jp][d] = (k[2jp][d], k[2jp+1][d]). The QK dot accumulates packed over a
// key PAIR, so the logit pair (s_j, s_j+1) emerges with no unpack/FADD/repack
// (R3 spent 4 scalar FADD + extra MOVs per 4 pairs on this). ~12% fewer issue
// slots/pair in a latency/issue-bound kernel.

#define HW_  (128*128)
#define WW_  128
#define CC_  64
#define LOG2E 1.44269504088896340736f

__device__ __forceinline__ unsigned long long pk2(float lo, float hi) {
    unsigned long long r;
    asm("mov.b64 %0, {%1, %2};" : "=l"(r) : "f"(lo), "f"(hi));
    return r;
}
__device__ __forceinline__ void upk2(unsigned long long v, float& lo, float& hi) {
    asm("mov.b64 {%0, %1}, %2;" : "=f"(lo), "=f"(hi) : "l"(v));
}
__device__ __forceinline__ unsigned long long ffma2(unsigned long long a, unsigned long long b, unsigned long long c) {
    unsigned long long d;
    asm("fma.rn.f32x2 %0, %1, %2, %3;" : "=l"(d) : "l"(a), "l"(b), "l"(c));
    return d;
}
__device__ __forceinline__ unsigned long long fmul2(unsigned long long a, unsigned long long b) {
    unsigned long long d;
    asm("mul.rn.f32x2 %0, %1, %2;" : "=l"(d) : "l"(a), "l"(b));
    return d;
}
__device__ __forceinline__ unsigned long long fadd2(unsigned long long a, unsigned long long b) {
    unsigned long long d;
    asm("add.rn.f32x2 %0, %1, %2;" : "=l"(d) : "l"(a), "l"(b));
    return d;
}
__device__ __forceinline__ float ex2(float x) {
    float r;
    asm("ex2.approx.f32 %0, %1;" : "=f"(r) : "f"(x));
    return r;
}

__global__ void __launch_bounds__(128, 4)
lepe_kernel(const float* __restrict__ temp,
            const float* __restrict__ cw,
            const float* __restrict__ cb,
            float* __restrict__ out)
{
    const int wh  = blockIdx.x;      // 0..2047
    const int h   = wh & 7;          // head
    const int win = wh >> 3;         // 0..255
    const int b   = win >> 6;        // batch
    const int wx  = win & 63;        // window column (x in [2*wx, 2*wx+1])
    const int t   = threadIdx.x;     // 0..127; owns queries t and t+128

    __shared__ __align__(16) float qS[256*8];
    __shared__ __align__(16) float kT[128*16];  // [key-pair jp][d] = (k[2jp][d], k[2jp+1][d])
    __shared__ __align__(16) float vS[262*8];   // 3 guard-zero tokens each side
    __shared__ __align__(16) float wS[9*8];
    __shared__ float bS[8];

    if (t < 24) { vS[t] = 0.f; vS[262*8 - 24 + t] = 0.f; }
    if (t < 72) wS[t] = cw[(h*8 + (t & 7))*9 + (t >> 3)];   // wS[tap][d]
    if (t < 8)  bS[t] = cb[h*8 + t];

    // Cooperative tile load: thread -> (d = t&7, y0 = t>>3 in 0..15), 8 steps.
    // The float2 per (y,d) IS the key pair for jp=y: single ST.64 into kT.
    {
        const int d  = t & 7;
        const int y0 = t >> 3;
        const size_t cbase = (size_t)(h*8 + d) * HW_ + 2*wx;
        const float* qg = temp + (size_t)(b*3 + 0)*CC_*HW_ + cbase;
        const float* kg = temp + (size_t)(b*3 + 1)*CC_*HW_ + cbase;
        const float* vg = temp + (size_t)(b*3 + 2)*CC_*HW_ + cbase;
        #pragma unroll
        for (int i = 0; i < 8; i++) {
            int y = y0 + i*16;
            float2 q2 = *(const float2*)(qg + (size_t)y*WW_);
            float2 k2 = *(const float2*)(kg + (size_t)y*WW_);
            float2 v2 = *(const float2*)(vg + (size_t)y*WW_);
            qS[(2*y  )*8 + d] = q2.x;  qS[(2*y+1)*8 + d] = q2.y;
            *(float2*)&kT[(y*8 + d)*2] = k2;
            vS[(3+2*y)*8 + d] = v2.x;  vS[(4+2*y)*8 + d] = v2.y;
        }
    }
    __syncthreads();

    // Two query rows per thread, each channel duplicated into both packed
    // halves so the dot product runs packed over a key pair. scale*log2(e)
    // folded in -> bare ex2.approx per (query, key).
    const float qscale = 0.35355339059327373f * LOG2E;  // 8^-0.5 * log2(e)
    const int tA = t, tB = t + 128;
    unsigned long long qA[8], qB[8];
    {
        float4 a0 = *(const float4*)&qS[tA*8];
        float4 a1 = *(const float4*)&qS[tA*8 + 4];
        float4 b0 = *(const float4*)&qS[tB*8];
        float4 b1 = *(const float4*)&qS[tB*8 + 4];
        qA[0] = pk2(a0.x*qscale, a0.x*qscale);  qA[1] = pk2(a0.y*qscale, a0.y*qscale);
        qA[2] = pk2(a0.z*qscale, a0.z*qscale);  qA[3] = pk2(a0.w*qscale, a0.w*qscale);
        qA[4] = pk2(a1.x*qscale, a1.x*qscale);  qA[5] = pk2(a1.y*qscale, a1.y*qscale);
        qA[6] = pk2(a1.z*qscale, a1.z*qscale);  qA[7] = pk2(a1.w*qscale, a1.w*qscale);
        qB[0] = pk2(b0.x*qscale, b0.x*qscale);  qB[1] = pk2(b0.y*qscale, b0.y*qscale);
        qB[2] = pk2(b0.z*qscale, b0.z*qscale);  qB[3] = pk2(b0.w*qscale, b0.w*qscale);
        qB[4] = pk2(b1.x*qscale, b1.x*qscale);  qB[5] = pk2(b1.y*qscale, b1.y*qscale);
        qB[6] = pk2(b1.z*qscale, b1.z*qscale);  qB[7] = pk2(b1.w*qscale, b1.w*qscale);
    }

    unsigned long long aA01 = 0ull, aA23 = 0ull, aA45 = 0ull, aA67 = 0ull;
    unsigned long long aB01 = 0ull, aB23 = 0ull, aB45 = 0ull, aB67 = 0ull;
    unsigned long long lA2 = 0ull, lB2 = 0ull;   // packed (sum over even keys, odd keys)

    const ulonglong2* kt   = (const ulonglong2*)kT;
    const ulonglong2* v128 = (const ulonglong2*)(vS + 24);  // token 0 of V

    #pragma unroll 2
    for (int jp = 0; jp < 128; jp++) {
        ulonglong2 k0 = kt[jp*4 + 0];   // (kj,kj1) for d0 | d1
        ulonglong2 k1 = kt[jp*4 + 1];   // d2 | d3
        ulonglong2 k2 = kt[jp*4 + 2];   // d4 | d5
        ulonglong2 k3 = kt[jp*4 + 3];   // d6 | d7
        ulonglong2 va = v128[(2*jp  )*2 + 0];   // v[2jp][0..3]
        ulonglong2 vb = v128[(2*jp  )*2 + 1];   // v[2jp][4..7]
        ulonglong2 vc = v128[(2*jp+1)*2 + 0];   // v[2jp+1][0..3]
        ulonglong2 vd = v128[(2*jp+1)*2 + 1];   // v[2jp+1][4..7]

        unsigned long long sA = fmul2(qA[0], k0.x);
        unsigned long long sB = fmul2(qB[0], k0.x);
        sA = ffma2(qA[1], k0.y, sA);  sB = ffma2(qB[1], k0.y, sB);
        sA = ffma2(qA[2], k1.x, sA);  sB = ffma2(qB[2], k1.x, sB);
        sA = ffma2(qA[3], k1.y, sA);  sB = ffma2(qB[3], k1.y, sB);
        sA = ffma2(qA[4], k2.x, sA);  sB = ffma2(qB[4], k2.x, sB);
        sA = ffma2(qA[5], k2.y, sA);  sB = ffma2(qB[5], k2.y, sB);
        sA = ffma2(qA[6], k3.x, sA);  sB = ffma2(qB[6], k3.x, sB);
        sA = ffma2(qA[7], k3.y, sA);  sB = ffma2(qB[7], k3.y, sB);

        float sA0, sA1, sB0, sB1;
        upk2(sA, sA0, sA1);
        upk2(sB, sB0, sB1);
        float pA0 = ex2(sA0), pA1 = ex2(sA1);
        float pB0 = ex2(sB0), pB1 = ex2(sB1);
        lA2 = fadd2(lA2, pk2(pA0, pA1));
        lB2 = fadd2(lB2, pk2(pB0, pB1));

        unsigned long long ppA0 = pk2(pA0, pA0);
        unsigned long long ppA1 = pk2(pA1, pA1);
        unsigned long long ppB0 = pk2(pB0, pB0);
        unsigned long long ppB1 = pk2(pB1, pB1);
        aA01 = ffma2(ppA0, va.x, aA01);  aA23 = ffma2(ppA0, va.y, aA23);
        aA45 = ffma2(ppA0, vb.x, aA45);  aA67 = ffma2(ppA0, vb.y, aA67);
        aA01 = ffma2(ppA1, vc.x, aA01);  aA23 = ffma2(ppA1, vc.y, aA23);
        aA45 = ffma2(ppA1, vd.x, aA45);  aA67 = ffma2(ppA1, vd.y, aA67);
        aB01 = ffma2(ppB0, va.x, aB01);  aB23 = ffma2(ppB0, va.y, aB23);
        aB45 = ffma2(ppB0, vb.x, aB45);  aB67 = ffma2(ppB0, vb.y, aB67);
        aB01 = ffma2(ppB1, vc.x, aB01);  aB23 = ffma2(ppB1, vc.y, aB23);
        aB45 = ffma2(ppB1, vd.x, aB45);  aB67 = ffma2(ppB1, vd.y, aB67);
    }

    float lAe, lAo, lBe, lBo;
    upk2(lA2, lAe, lAo);
    upk2(lB2, lBe, lBo);
    const float invA = 1.0f / (lAe + lAo);
    const float invB = 1.0f / (lBe + lBo);

    // Epilogue per owned query token: softmax normalize + LePE depthwise 3x3
    // conv on the V tile in SMEM, then one float4-pair store.
    #pragma unroll
    for (int qi = 0; qi < 2; qi++) {
        const int tok = qi ? tB : tA;
        const float inv = qi ? invB : invA;
        float o[8];
        if (qi == 0) {
            upk2(aA01, o[0], o[1]); upk2(aA23, o[2], o[3]);
            upk2(aA45, o[4], o[5]); upk2(aA67, o[6], o[7]);
        } else {
            upk2(aB01, o[0], o[1]); upk2(aB23, o[2], o[3]);
            upk2(aB45, o[4], o[5]); upk2(aB67, o[6], o[7]);
        }

        const int y  = tok >> 1;
        const int xi = tok & 1;
        float r[8];
        #pragma unroll
        for (int d = 0; d < 8; d++) r[d] = bS[d];
        #pragma unroll
        for (int ky = 0; ky < 3; ky++) {
            #pragma unroll
            for (int kx = 0; kx < 3; kx++) {
                int dxi = xi + kx - 1;
                if (dxi >= 0 && dxi <= 1) {
                    int ptok = tok + (ky - 1)*2 + (kx - 1) + 3;  // padded index
                    const float4 va = *(const float4*)&vS[ptok*8];
                    const float4 vb = *(const float4*)&vS[ptok*8 + 4];
                    const float4 wa = *(const float4*)&wS[(ky*3 + kx)*8];
                    const float4 wb = *(const float4*)&wS[(ky*3 + kx)*8 + 4];
                    r[0] += va.x*wa.x;  r[1] += va.y*wa.y;
                    r[2] += va.z*wa.z;  r[3] += va.w*wa.w;
                    r[4] += vb.x*wb.x;  r[5] += vb.y*wb.y;
                    r[6] += vb.z*wb.z;  r[7] += vb.w*wb.w;
                }
            }
        }

        const size_t obase = ((size_t)b*HW_ + (size_t)y*WW_ + 2*wx + xi)*CC_ + h*8;
        float4 w0 = make_float4(o[0]*inv + r[0], o[1]*inv + r[1],
                                o[2]*inv + r[2], o[3]*inv + r[3]);
        float4 w1 = make_float4(o[4]*inv + r[4], o[5]*inv + r[5],
                                o[6]*inv + r[6], o[7]*inv + r[7]);
        *(float4*)(out + obase)     = w0;
        *(float4*)(out + obase + 4) = w1;
    }
}

extern "C" void kernel_launch(void* const* d_in, const int* in_sizes, int n_in,
                              void* d_out, int out_size)
{
    const float* temp = (const float*)d_in[0];
    const float* cw   = (const float*)d_in[1];
    const float* cb   = (const float*)d_in[2];
    float* out        = (float*)d_out;
    lepe_kernel<<<2048, 128>>>(temp, cw, cb, out);
}